// round 2
// baseline (speedup 1.0000x reference)
#include <cuda_runtime.h>
#include <cuda_bf16.h>

#define TILE 128
#define BK 32
#define PAD 132   // 132*4 bytes: 16B-aligned rows for LDS.128, bank offset 4 per k

// Block-activity mask scratch (max 8192x8192 problem => 256x256 blocks)
__device__ unsigned char d_bm[256 * 256];

// ---------------------------------------------------------------------------
// Kernel 1: pool element mask [N,K] into 32x32 block activity d_bm[Nb,Kb]
// ---------------------------------------------------------------------------
__global__ void blockmask_kernel(const int* __restrict__ mask, int K, int Kb) {
    int nb = blockIdx.x / Kb;
    int kb = blockIdx.x - nb * Kb;
    int r  = threadIdx.x >> 3;       // 0..31 row within tile
    int c4 = threadIdx.x & 7;        // 0..7  int4 within row
    const int4* p = (const int4*)(mask + (size_t)(nb * 32 + r) * K + kb * 32 + c4 * 4);
    int4 v = *p;
    int any = __syncthreads_or(v.x | v.y | v.z | v.w);
    if (threadIdx.x == 0) d_bm[nb * Kb + kb] = any ? 1 : 0;
}

// ---------------------------------------------------------------------------
// Kernel 2: block-sparse fp32 GEMM  C[M,N] = A[M,K] * W[N,K]^T + bias
// 128x128 CTA tile, BK=32 (aligned to mask blocks), 256 threads, 8x8/thread.
// Skips K-chunks where all 4 N-subblocks are masked off; skips W-row loads
// for individually-masked 32-row groups inside active chunks.
// ---------------------------------------------------------------------------
__global__ __launch_bounds__(256, 2)
void gemm_kernel(const float* __restrict__ A, const float* __restrict__ W,
                 const float* __restrict__ bias, float* __restrict__ C,
                 int M, int N, int K, int Kb)
{
    __shared__ float As[BK * PAD];
    __shared__ float Ws[BK * PAD];
    __shared__ unsigned char s_flags[4 * 256];   // [n-subblock 0..3][kb]
    __shared__ unsigned short s_list[256];       // compacted active kb list
    __shared__ int s_count;

    const int tid = threadIdx.x;
    const int n0  = blockIdx.x * TILE;
    const int m0  = blockIdx.y * TILE;
    const int nb0 = n0 >> 5;

    // Load this CTA's 4 block-mask rows into smem
    for (int i = tid; i < 4 * Kb; i += 256) {
        int r = i / Kb;
        int c = i - r * Kb;
        s_flags[r * 256 + c] = d_bm[(nb0 + r) * Kb + c];
    }
    __syncthreads();
    if (tid == 0) {
        int cnt = 0;
        for (int kb = 0; kb < Kb; kb++) {
            if (s_flags[kb] | s_flags[256 + kb] | s_flags[512 + kb] | s_flags[768 + kb])
                s_list[cnt++] = (unsigned short)kb;
        }
        s_count = cnt;
    }
    __syncthreads();
    const int cnt = s_count;

    float acc[8][8];
#pragma unroll
    for (int i = 0; i < 8; i++)
#pragma unroll
        for (int j = 0; j < 8; j++) acc[i][j] = 0.f;

    const int rm = tid & 15;   // micro-tile row group
    const int rn = tid >> 4;   // micro-tile col group

    // load coords: 1024 float4 loads per tile, 4 per thread
    const int lrow = tid >> 3;       // base row 0..31 (+32*i)
    const int lk   = (tid & 7) * 4;  // k offset within chunk

    // hoisted base pointers for the compute phase (keep inner loop FFMA+LDS only)
    const float* As_p0 = As + rm * 4;
    const float* As_p1 = As + rm * 4 + 64;
    const float* Ws_p0 = Ws + rn * 4;
    const float* Ws_p1 = Ws + rn * 4 + 64;

    float4 ra[4], rw[4];

#define LDG_TILE(KB)                                                                  \
    {                                                                                 \
        const int kb_ = (KB);                                                         \
        const int fl0 = s_flags[((lrow) >> 5) * 256 + kb_];                           \
        const int fl1 = s_flags[((lrow + 32) >> 5) * 256 + kb_];                      \
        const int fl2 = s_flags[((lrow + 64) >> 5) * 256 + kb_];                      \
        const int fl3 = s_flags[((lrow + 96) >> 5) * 256 + kb_];                      \
        const int flags4[4] = {fl0, fl1, fl2, fl3};                                   \
        _Pragma("unroll")                                                             \
        for (int i = 0; i < 4; i++) {                                                 \
            const int row = lrow + 32 * i;                                            \
            ra[i] = *(const float4*)(A + (size_t)(m0 + row) * K + kb_ * 32 + lk);     \
            if (flags4[i]) {                                                          \
                rw[i] = *(const float4*)(W + (size_t)(n0 + row) * K + kb_ * 32 + lk); \
            } else {                                                                  \
                rw[i] = make_float4(0.f, 0.f, 0.f, 0.f);                              \
            }                                                                         \
        }                                                                             \
    }

#define STS_TILE()                                                                \
    {                                                                             \
        _Pragma("unroll")                                                         \
        for (int i = 0; i < 4; i++) {                                             \
            const int row = lrow + 32 * i;                                        \
            As[(lk + 0) * PAD + row] = ra[i].x;                                   \
            As[(lk + 1) * PAD + row] = ra[i].y;                                   \
            As[(lk + 2) * PAD + row] = ra[i].z;                                   \
            As[(lk + 3) * PAD + row] = ra[i].w;                                   \
            Ws[(lk + 0) * PAD + row] = rw[i].x;                                   \
            Ws[(lk + 1) * PAD + row] = rw[i].y;                                   \
            Ws[(lk + 2) * PAD + row] = rw[i].z;                                   \
            Ws[(lk + 3) * PAD + row] = rw[i].w;                                   \
        }                                                                         \
    }

#define COMPUTE_TILE()                                                            \
    {                                                                             \
        _Pragma("unroll 8")                                                       \
        for (int k = 0; k < BK; k++) {                                            \
            float4 a0 = *(const float4*)(As_p0 + k * PAD);                        \
            float4 a1 = *(const float4*)(As_p1 + k * PAD);                        \
            float4 b0 = *(const float4*)(Ws_p0 + k * PAD);                        \
            float4 b1 = *(const float4*)(Ws_p1 + k * PAD);                        \
            float av[8] = {a0.x, a0.y, a0.z, a0.w, a1.x, a1.y, a1.z, a1.w};       \
            float bv[8] = {b0.x, b0.y, b0.z, b0.w, b1.x, b1.y, b1.z, b1.w};       \
            _Pragma("unroll")                                                     \
            for (int i2 = 0; i2 < 8; i2++)                                        \
                _Pragma("unroll")                                                 \
                for (int j2 = 0; j2 < 8; j2++)                                    \
                    acc[i2][j2] += av[i2] * bv[j2];                               \
        }                                                                         \
    }

    if (cnt > 0) {
        LDG_TILE((int)s_list[0]);
        STS_TILE();
        __syncthreads();
        for (int it = 1; it < cnt; it++) {
            LDG_TILE((int)s_list[it]);   // prefetch next chunk into registers
            COMPUTE_TILE();              // overlap compute with in-flight LDGs
            __syncthreads();
            STS_TILE();
            __syncthreads();
        }
        COMPUTE_TILE();
    }

    // Epilogue: add bias, write fp32 output
    float4 blo = *(const float4*)(bias + n0 + rn * 4);
    float4 bhi = *(const float4*)(bias + n0 + rn * 4 + 64);
#pragma unroll
    for (int i = 0; i < 8; i++) {
        const int m = m0 + ((i < 4) ? (rm * 4 + i) : (64 + rm * 4 + (i - 4)));
        float* cp = C + (size_t)m * N + n0;
        float4 o0 = make_float4(acc[i][0] + blo.x, acc[i][1] + blo.y,
                                acc[i][2] + blo.z, acc[i][3] + blo.w);
        float4 o1 = make_float4(acc[i][4] + bhi.x, acc[i][5] + bhi.y,
                                acc[i][6] + bhi.z, acc[i][7] + bhi.w);
        *(float4*)(cp + rn * 4)      = o0;
        *(float4*)(cp + rn * 4 + 64) = o1;
    }
#undef LDG_TILE
#undef STS_TILE
#undef COMPUTE_TILE
}

// ---------------------------------------------------------------------------
// Launch: inputs are [data(B,S,K) f32, mask(N,K) i32, weight(N,K) f32, bias(N) f32]
// ---------------------------------------------------------------------------
extern "C" void kernel_launch(void* const* d_in, const int* in_sizes, int n_in,
                              void* d_out, int out_size) {
    const float* data   = (const float*)d_in[0];
    const int*   mask   = (const int*)d_in[1];
    const float* weight = (const float*)d_in[2];
    const float* bias   = (const float*)d_in[3];
    float* out = (float*)d_out;

    const int N = in_sizes[3];
    const int K = in_sizes[1] / N;
    const int M = in_sizes[0] / K;
    const int Kb = K / 32;
    const int Nb = N / 32;

    blockmask_kernel<<<Nb * Kb, 256>>>(mask, K, Kb);

    dim3 grid(N / TILE, M / TILE);
    gemm_kernel<<<grid, 256>>>(data, weight, bias, out, M, N, K, Kb);
}

// round 6
// speedup vs baseline: 2.5722x; 2.5722x over previous
#include <cuda_runtime.h>
#include <cuda_bf16.h>
#include <cstdint>

// ---------------------------------------------------------------------------
// Static device scratch
// ---------------------------------------------------------------------------
#define MMAX 4096
#define KMAX 4096
__device__ unsigned char d_bm[256 * 256];
__device__ __nv_bfloat16 d_A2[(size_t)MMAX * 2 * KMAX];   // 64 MB: A hi/lo packed
__device__ __nv_bfloat16 d_W2[(size_t)MMAX * 2 * KMAX];   // 64 MB: W hi/lo packed

// ---------------------------------------------------------------------------
// PTX helpers (sm_80-level features only: cp.async, ldmatrix, mma.sync)
// ---------------------------------------------------------------------------
__device__ __forceinline__ uint32_t smem_addr(const void* p) {
    uint32_t a;
    asm("{ .reg .u64 t; cvta.to.shared.u64 t, %1; cvt.u32.u64 %0, t; }" : "=r"(a) : "l"(p));
    return a;
}
__device__ __forceinline__ void cp16(uint32_t dst, const void* src, int srcsz) {
    asm volatile("cp.async.cg.shared.global [%0], [%1], 16, %2;"
                 :: "r"(dst), "l"(src), "r"(srcsz) : "memory");
}
__device__ __forceinline__ void cp_commit() { asm volatile("cp.async.commit_group;" ::: "memory"); }
template <int N> __device__ __forceinline__ void cp_wait() {
    asm volatile("cp.async.wait_group %0;" :: "n"(N) : "memory");
}
__device__ __forceinline__ void ldmx4(uint32_t* r, uint32_t a) {
    asm volatile("ldmatrix.sync.aligned.m8n8.x4.shared.b16 {%0,%1,%2,%3}, [%4];"
                 : "=r"(r[0]), "=r"(r[1]), "=r"(r[2]), "=r"(r[3]) : "r"(a));
}
__device__ __forceinline__ void mma16816(float* c, const uint32_t* a, const uint32_t* b) {
    asm volatile(
        "mma.sync.aligned.m16n8k16.row.col.f32.bf16.bf16.f32 "
        "{%0,%1,%2,%3}, {%4,%5,%6,%7}, {%8,%9}, {%0,%1,%2,%3};"
        : "+f"(c[0]), "+f"(c[1]), "+f"(c[2]), "+f"(c[3])
        : "r"(a[0]), "r"(a[1]), "r"(a[2]), "r"(a[3]), "r"(b[0]), "r"(b[1]));
}

#define SWZ(o) ((o) ^ (((o) >> 3) & 0x70))

// Dynamic smem layout (base 1024-aligned; 32KB per buffer: A 16KB + W 16KB)
#define SM_A(b)   ((b) * 32768)
#define SM_W(b)   ((b) * 32768 + 16384)
#define SM_FLAGS  65536   // 4*256 bytes
#define SM_LIST   66560   // 256 * u16
#define SM_BIAS   67072   // 128 * f32
#define SM_MISC   67584   // [0]=count
#define SMEM_TOTAL 68608

// ---------------------------------------------------------------------------
// Kernel 1: pool element mask [N,K] into 32x32 block activity d_bm[Nb,Kb]
// ---------------------------------------------------------------------------
__global__ void blockmask_kernel(const int* __restrict__ mask, int K, int Kb) {
    int nb = blockIdx.x / Kb;
    int kb = blockIdx.x - nb * Kb;
    int r  = threadIdx.x >> 3;
    int c4 = threadIdx.x & 7;
    const int4* p = (const int4*)(mask + (size_t)(nb * 32 + r) * K + kb * 32 + c4 * 4);
    int4 v = *p;
    int any = __syncthreads_or(v.x | v.y | v.z | v.w);
    if (threadIdx.x == 0) d_bm[nb * Kb + kb] = any ? 1 : 0;
}

// ---------------------------------------------------------------------------
// Kernel 2: pack fp32 -> bf16 hi/lo, chunk-interleaved per 32-K-chunk:
//   out[m][c*64 + j]      = bf16(x)     (j = k&31, c = k>>5)
//   out[m][c*64 + 32 + j] = bf16(x - hi)
// Each packed row chunk = 128 bytes = one SW128 swizzle atom row.
// ---------------------------------------------------------------------------
__device__ __forceinline__ void pack_row(const float* __restrict__ src,
                                         __nv_bfloat16* __restrict__ dst, int K) {
    const int m = blockIdx.x;
    const float* row = src + (size_t)m * K;
    __nv_bfloat16* out = dst + (size_t)m * 2 * K;
    for (int p = threadIdx.x; p < (K >> 1); p += blockDim.x) {
        int k = p << 1;
        float2 v = *(const float2*)(row + k);
        __nv_bfloat16 h0 = __float2bfloat16(v.x);
        __nv_bfloat16 h1 = __float2bfloat16(v.y);
        __nv_bfloat162 hv; hv.x = h0; hv.y = h1;
        __nv_bfloat162 lv;
        lv.x = __float2bfloat16(v.x - __bfloat162float(h0));
        lv.y = __float2bfloat16(v.y - __bfloat162float(h1));
        int c = k >> 5, j = k & 31;
        *(__nv_bfloat162*)(out + (size_t)c * 64 + j)      = hv;
        *(__nv_bfloat162*)(out + (size_t)c * 64 + 32 + j) = lv;
    }
}
__global__ void pack_a_kernel(const float* __restrict__ src, int K) { pack_row(src, d_A2, K); }
__global__ void pack_w_kernel(const float* __restrict__ src, int K) { pack_row(src, d_W2, K); }

// ---------------------------------------------------------------------------
// Kernel 3: block-sparse bf16x3 GEMM via mma.sync (HMMA.16816.F32.BF16).
// C[M,N] = A*W^T + bias. CTA: 128x128, 8 warps as 4(m) x 2(n), warp = 32m x 64n.
// K consumed in 32-chunks (one SW128 atom row: hi[32]|lo[32] bf16).
// 3 passes per chunk: Ahi*Whi, Ahi*Wlo, Alo*Whi.
// Double-buffered cp.async; zfill (src-size 0) = per-32-row W masking.
// ---------------------------------------------------------------------------
__global__ __launch_bounds__(256)
void mma_gemm(const float* __restrict__ bias, float* __restrict__ C,
              int M, int N, int K, int Kb)
{
    extern __shared__ __align__(1024) char sm[];
    const int tid  = threadIdx.x;
    const int lane = tid & 31;
    const int wid  = tid >> 5;
    const int n0 = blockIdx.x * 128;
    const int m0 = blockIdx.y * 128;
    const int nb0 = n0 >> 5;
    const size_t twoK = (size_t)2 * K;

    unsigned char*  s_flags = (unsigned char*)(sm + SM_FLAGS);
    unsigned short* s_list  = (unsigned short*)(sm + SM_LIST);
    float*          s_bias  = (float*)(sm + SM_BIAS);
    volatile int*   s_misc  = (volatile int*)(sm + SM_MISC);
    const uint32_t smb = smem_addr(sm);

    for (int i = tid; i < 4 * Kb; i += 256) {
        int r = i / Kb, c = i - r * Kb;
        s_flags[r * 256 + c] = d_bm[(size_t)(nb0 + r) * Kb + c];
    }
    if (tid < 128) s_bias[tid] = bias[n0 + tid];
    __syncthreads();
    if (tid == 0) {
        int cnt = 0;
        for (int kb = 0; kb < Kb; kb++)
            if (s_flags[kb] | s_flags[256 + kb] | s_flags[512 + kb] | s_flags[768 + kb])
                s_list[cnt++] = (unsigned short)kb;
        s_misc[0] = cnt;
    }
    __syncthreads();
    const int cnt = s_misc[0];

    // Warp tiling
    const int warp_m = wid & 3;        // 0..3  -> m offset 32*warp_m
    const int warp_n = wid >> 2;       // 0..1  -> n offset 64*warp_n
    const int wm32 = warp_m * 32;
    const int wn64 = warp_n * 64;

    // ldmatrix per-lane row/col components
    const int a_row = ((lane >> 3) & 1) * 8 + (lane & 7);  // + kseg via lane>>4
    const int a_ks  = (lane >> 4) & 1;
    const int b_r   = lane & 7;
    const int b_ks  = (lane >> 3) & 1;
    const int b_ts  = (lane >> 4) & 1;

    // cp.async coords: 1024 x 16B per 32KB buffer half pair; 4 iters x 256 thr
    const int lrow = tid >> 3;        // 0..31 (+32*i)
    const int lc16 = tid & 7;         // 16B segment within 128B row

    float acc[2][8][4];
#pragma unroll
    for (int mt = 0; mt < 2; mt++)
#pragma unroll
        for (int nt = 0; nt < 8; nt++)
#pragma unroll
            for (int q = 0; q < 4; q++) acc[mt][nt][q] = 0.f;

#define LOAD_CHUNK(KB, BUF)                                                        \
    do {                                                                           \
        const int kb_ = (KB);                                                      \
        const uint32_t ab_ = smb + SM_A(BUF);                                      \
        const uint32_t wb_ = smb + SM_W(BUF);                                      \
        const __nv_bfloat16* ga_ = d_A2 + (size_t)m0 * twoK + (size_t)kb_ * 64;    \
        const __nv_bfloat16* gw_ = d_W2 + (size_t)n0 * twoK + (size_t)kb_ * 64;    \
        _Pragma("unroll")                                                          \
        for (int it_ = 0; it_ < 4; it_++) {                                        \
            const int row_ = lrow + it_ * 32;                                      \
            const uint32_t so_ = SWZ(row_ * 128 + lc16 * 16);                      \
            cp16(ab_ + so_, ga_ + (size_t)row_ * twoK + lc16 * 8, 16);             \
            const int sz_ = s_flags[((row_ >> 5) << 8) + kb_] ? 16 : 0;            \
            cp16(wb_ + so_, gw_ + (size_t)row_ * twoK + lc16 * 8, sz_);            \
        }                                                                          \
        cp_commit();                                                               \
    } while (0)

    if (cnt > 0) {
        LOAD_CHUNK((int)s_list[0], 0);
        for (int i = 0; i < cnt; i++) {
            const int cur = i & 1;
            if (i + 1 < cnt) {
                LOAD_CHUNK((int)s_list[i + 1], cur ^ 1);
                cp_wait<1>();          // chunk i landed; i+1 may remain in flight
            } else {
                cp_wait<0>();
            }
            __syncthreads();           // tile visible to all warps

            const uint32_t ab = smb + SM_A(cur);
            const uint32_t wb = smb + SM_W(cur);
#pragma unroll
            for (int p = 0; p < 3; p++) {
                const int Ab = (p == 2) ? 64 : 0;   // A: hi,hi,lo
                const int Bb = (p == 1) ? 64 : 0;   // W: hi,lo,hi
#pragma unroll
                for (int s = 0; s < 2; s++) {
                    uint32_t afr[2][4];
#pragma unroll
                    for (int mt = 0; mt < 2; mt++)
                        ldmx4(afr[mt], ab + SWZ((wm32 + mt * 16 + a_row) * 128 +
                                                Ab + s * 32 + a_ks * 16));
                    uint32_t bfr[4][4];
#pragma unroll
                    for (int j = 0; j < 4; j++)
                        ldmx4(bfr[j], wb + SWZ((wn64 + (2 * j + b_ts) * 8 + b_r) * 128 +
                                               Bb + s * 32 + b_ks * 16));
#pragma unroll
                    for (int mt = 0; mt < 2; mt++)
#pragma unroll
                        for (int nt = 0; nt < 8; nt++)
                            mma16816(acc[mt][nt], afr[mt], &bfr[nt >> 1][(nt & 1) * 2]);
                }
            }
            __syncthreads();           // all warps done with buffer cur
        }
    }

    // Epilogue: acc + bias -> C (covers cnt==0: acc stays zero)
#pragma unroll
    for (int mt = 0; mt < 2; mt++) {
        const int gm = m0 + wm32 + mt * 16 + (lane >> 2);
#pragma unroll
        for (int nt = 0; nt < 8; nt++) {
            const int bn = wn64 + nt * 8 + (lane & 3) * 2;
            const float b0 = s_bias[bn], b1 = s_bias[bn + 1];
            float2 o0 = make_float2(acc[mt][nt][0] + b0, acc[mt][nt][1] + b1);
            float2 o1 = make_float2(acc[mt][nt][2] + b0, acc[mt][nt][3] + b1);
            *(float2*)(C + (size_t)gm * N + n0 + bn)       = o0;
            *(float2*)(C + (size_t)(gm + 8) * N + n0 + bn) = o1;
        }
    }
#undef LOAD_CHUNK
}

// ---------------------------------------------------------------------------
// Launch: inputs [data(B,S,K) f32, mask(N,K) i32, weight(N,K) f32, bias(N) f32]
// ---------------------------------------------------------------------------
extern "C" void kernel_launch(void* const* d_in, const int* in_sizes, int n_in,
                              void* d_out, int out_size) {
    const float* data   = (const float*)d_in[0];
    const int*   mask   = (const int*)d_in[1];
    const float* weight = (const float*)d_in[2];
    const float* bias   = (const float*)d_in[3];
    float* out = (float*)d_out;

    const int N = in_sizes[3];
    const int K = in_sizes[1] / N;
    const int M = in_sizes[0] / K;
    const int Kb = K / 32;
    const int Nb = N / 32;

    cudaFuncSetAttribute(mma_gemm, cudaFuncAttributeMaxDynamicSharedMemorySize, SMEM_TOTAL);

    blockmask_kernel<<<Nb * Kb, 256>>>(mask, K, Kb);
    pack_a_kernel<<<M, 256>>>(data, K);
    pack_w_kernel<<<N, 256>>>(weight, K);

    dim3 grid(N / 128, M / 128);
    mma_gemm<<<grid, 256, SMEM_TOTAL>>>(bias, out, M, N, K, Kb);
}